// round 13
// baseline (speedup 1.0000x reference)
#include <cuda_runtime.h>
#include <cuda_bf16.h>
#include <cstdint>

// Problem constants (fixed shapes per reference)
#define Bn   8
#define Nn   1024
#define Fin  128
#define Cc   128
#define Ef   64
#define Hh   4
#define NEG  0.2f
#define ROWS (Bn * Nn)          // 8192
#define ICHUNK 16               // i-rows per block in main kernel
#define NBKT   256              // (64 i-chunks) x (4 j-tiles)
#define BCAP   1024             // bucket capacity (mean occupancy ~128)

// Scratch (device globals — no allocation allowed).
// g_bcnt/g_bread start BSS-zero and are self-reset by the main kernel at the
// end of every run, so each launch sequence starts from zeroed counters.
__device__ float4         g_S  [ROWS];      // s = src @ (W_lin@a_src)
__device__ float4         g_D  [ROWS];      // d = src @ (W_lin@a_dst)
__device__ float4         g_P  [ROWS];      // p = src @ (W_edge@a_edge)
__device__ float4         g_ES [ROWS];      // exp(s)
__device__ float4         g_ES2[ROWS];      // exp(0.2 s)
__device__ float4         g_ED [ROWS];      // exp(d)
__device__ float4         g_ED2[ROWS];      // exp(0.2 d)
__device__ float4         g_U  [ROWS];      // exp(s + p)
__device__ float4         g_U2 [ROWS];      // exp(0.2(s + p))
__device__ float4         g_W  [ROWS];      // exp(d - p)
__device__ float4         g_W2 [ROWS];      // exp(0.2(d - p))
__device__ int            g_bcnt [NBKT];    // per-tile edge counts
__device__ int            g_bread[NBKT];    // consumer tickets (self-reset)
__device__ unsigned short g_bdata[NBKT * BCAP];  // packed cells: i_loc<<8 | j_loc

// ---------------------------------------------------------------------------
// Kernel 1: PREP — bucket edges by output tile, fold weights M per block
// (cheap: each thread streams one W row once), then warp-per-row
// projections + exponentials.
// ---------------------------------------------------------------------------
__global__ __launch_bounds__(256) void prep_kernel(
        const float* __restrict__ src,
        const int*   __restrict__ edge_index, int E,
        const float* __restrict__ W_lin,
        const float* __restrict__ a_src,
        const float* __restrict__ a_dst,
        const float* __restrict__ W_edge,
        const float* __restrict__ a_edge) {
    // ---- phase A: bucket fill (independent; g_bcnt zeroed by prior run)
    {
        const int t  = blockIdx.x * blockDim.x + threadIdx.x;
        const int nt = gridDim.x * blockDim.x;
        for (int e = t; e < E; e += nt) {
            const int i = edge_index[e];
            const int j = edge_index[E + e];
            const int bkt = (i >> 4) * 4 + (j >> 8);
            const int pos = atomicAdd(&g_bcnt[bkt], 1);
            if (pos < BCAP)
                g_bdata[bkt * BCAP + pos] =
                    (unsigned short)(((i & 15) << 8) | (j & 255));
        }
    }

    // ---- phase B: fold M into smem. t<128: W_lin row t -> cols 0-7;
    //      t>=128: W_edge row t-128 -> cols 8-11. One W-row stream each.
    __shared__ float sM[Fin * 12];
    {
        const int t = threadIdx.x;
        if (t < 128) {
            const int f = t;
            float acc[8];
            #pragma unroll
            for (int h = 0; h < 8; h++) acc[h] = 0.0f;
            const float4* __restrict__ as4 = reinterpret_cast<const float4*>(a_src);
            const float4* __restrict__ ad4 = reinterpret_cast<const float4*>(a_dst);
            #pragma unroll 4
            for (int c = 0; c < Cc; c++) {
                const float wv = __ldg(&W_lin[f * Cc + c]);
                const float4 as = __ldg(&as4[c]);   // broadcast
                const float4 ad = __ldg(&ad4[c]);
                acc[0] += wv * as.x; acc[1] += wv * as.y;
                acc[2] += wv * as.z; acc[3] += wv * as.w;
                acc[4] += wv * ad.x; acc[5] += wv * ad.y;
                acc[6] += wv * ad.z; acc[7] += wv * ad.w;
            }
            #pragma unroll
            for (int h = 0; h < 8; h++) sM[f * 12 + h] = acc[h];
        } else {
            const int f = t - 128;
            float acc[4] = {0, 0, 0, 0};
            const float4* __restrict__ ae4 = reinterpret_cast<const float4*>(a_edge);
            #pragma unroll 4
            for (int d = 0; d < Ef; d++) {
                const float wv = __ldg(&W_edge[f * Ef + d]);
                const float4 ae = __ldg(&ae4[d]);   // broadcast
                acc[0] += wv * ae.x; acc[1] += wv * ae.y;
                acc[2] += wv * ae.z; acc[3] += wv * ae.w;
            }
            #pragma unroll
            for (int h = 0; h < 4; h++) sM[f * 12 + 8 + h] = acc[h];
        }
    }
    __syncthreads();

    // ---- phase C: rows (warp per row)
    const int gwarp  = (blockIdx.x * blockDim.x + threadIdx.x) >> 5;
    const int lane   = threadIdx.x & 31;
    const int nwarps = (gridDim.x * blockDim.x) >> 5;

    for (int r = gwarp; r < ROWS; r += nwarps) {
        const float4 sv = reinterpret_cast<const float4*>(src + (size_t)r * Fin)[lane];
        float acc[12];
        #pragma unroll
        for (int h = 0; h < 12; h++) acc[h] = 0.0f;

        const float vals[4] = {sv.x, sv.y, sv.z, sv.w};
        #pragma unroll
        for (int k = 0; k < 4; k++) {
            const int f = lane * 4 + k;
            const float x = vals[k];
            #pragma unroll
            for (int h = 0; h < 12; h++) acc[h] += x * sM[f * 12 + h];
        }
        #pragma unroll
        for (int o = 16; o > 0; o >>= 1) {
            #pragma unroll
            for (int h = 0; h < 12; h++)
                acc[h] += __shfl_xor_sync(0xffffffffu, acc[h], o);
        }
        if (lane == 0) {
            float4 s = make_float4(acc[0], acc[1], acc[2],  acc[3]);
            float4 d = make_float4(acc[4], acc[5], acc[6],  acc[7]);
            float4 p = make_float4(acc[8], acc[9], acc[10], acc[11]);
            g_S[r] = s;  g_D[r] = d;  g_P[r] = p;
            g_ES [r] = make_float4(__expf(s.x), __expf(s.y), __expf(s.z), __expf(s.w));
            g_ES2[r] = make_float4(__expf(NEG*s.x), __expf(NEG*s.y), __expf(NEG*s.z), __expf(NEG*s.w));
            g_ED [r] = make_float4(__expf(d.x), __expf(d.y), __expf(d.z), __expf(d.w));
            g_ED2[r] = make_float4(__expf(NEG*d.x), __expf(NEG*d.y), __expf(NEG*d.z), __expf(NEG*d.w));
            float4 sp = make_float4(s.x + p.x, s.y + p.y, s.z + p.z, s.w + p.w);
            float4 dp = make_float4(d.x - p.x, d.y - p.y, d.z - p.z, d.w - p.w);
            g_U [r] = make_float4(__expf(sp.x), __expf(sp.y), __expf(sp.z), __expf(sp.w));
            g_U2[r] = make_float4(__expf(NEG*sp.x), __expf(NEG*sp.y), __expf(NEG*sp.z), __expf(NEG*sp.w));
            g_W [r] = make_float4(__expf(dp.x), __expf(dp.y), __expf(dp.z), __expf(dp.w));
            g_W2[r] = make_float4(__expf(NEG*dp.x), __expf(NEG*dp.y), __expf(NEG*dp.z), __expf(NEG*dp.w));
        }
    }
}

// ---------------------------------------------------------------------------
// Kernel 2: fused MAIN. Block = (j-tile, i-chunk, b). Builds a 4 KB smem
// multiplicity tile from its edge bucket, streams 16x256 quads. Clean
// warp-iters (ballot says no edges) run the 2-stream fmax body; edge iters
// load u/u2 and select; c>=2 (duplicate edges) take the exact __expf path.
// After consumption, the last of the 8 b-blocks per bucket resets the
// counters so the next run starts from zero.
// ---------------------------------------------------------------------------
__global__ __launch_bounds__(256) void attn_main_kernel(float4* __restrict__ out) {
    __shared__ unsigned scnt[1024];            // uint8[4096] packed

    const int jt = blockIdx.x;                 // 0..3
    const int ic = blockIdx.y;                 // 0..63
    const int b  = blockIdx.z;
    const int j  = jt * 256 + threadIdx.x;
    const int i0 = ic * ICHUNK;
    const int rj = b * Nn + j;
    const int bkt = ic * 4 + jt;

    // build smem cnt from this tile's bucket
    #pragma unroll
    for (int k = 0; k < 4; k++) scnt[threadIdx.x + k * 256] = 0u;
    __syncthreads();
    const int nb = g_bcnt[bkt];
    {
        const int n = nb < BCAP ? nb : BCAP;
        for (int k = threadIdx.x; k < n; k += 256) {
            const unsigned cell = g_bdata[bkt * BCAP + k];   // i_loc<<8 | j_loc
            atomicAdd(&scnt[cell >> 2], 1u << ((cell & 3) * 8));
        }
    }
    __syncthreads();

    // ticket: last of the Bn consumers resets the bucket counters
    if (threadIdx.x == 0) {
        const int tk = atomicAdd(&g_bread[bkt], 1);
        if (tk == Bn - 1) { g_bcnt[bkt] = 0; g_bread[bkt] = 0; }
    }

    const unsigned char* sc8 = reinterpret_cast<const unsigned char*>(scnt);

    // j-side tables in registers
    const float4 ed  = __ldg(&g_ED [rj]);
    const float4 ed2 = __ldg(&g_ED2[rj]);
    const float4 w   = __ldg(&g_W  [rj]);
    const float4 w2  = __ldg(&g_W2 [rj]);

    const float4* __restrict__ esrow  = g_ES  + b * Nn + i0;
    const float4* __restrict__ es2row = g_ES2 + b * Nn + i0;
    const float4* __restrict__ urow   = g_U   + b * Nn + i0;
    const float4* __restrict__ u2row  = g_U2  + b * Nn + i0;
    float4* __restrict__ optr = out + ((size_t)(b * Nn + i0)) * Nn + j;

    #pragma unroll 4
    for (int i = 0; i < ICHUNK; i++) {
        const unsigned c = sc8[i * 256 + threadIdx.x];   // conflict-free LDS
        const unsigned any = __ballot_sync(0xffffffffu, c != 0u);

        const float4 es  = __ldg(esrow  + i);   // broadcast across warp
        const float4 es2 = __ldg(es2row + i);

        float4 e;
        e.x = fmaxf(es.x * ed.x, es2.x * ed2.x);
        e.y = fmaxf(es.y * ed.y, es2.y * ed2.y);
        e.z = fmaxf(es.z * ed.z, es2.z * ed2.z);
        e.w = fmaxf(es.w * ed.w, es2.w * ed2.w);

        if (any) {   // warp-uniform: only iters containing an edge pay this
            const float4 u  = __ldg(urow  + i);
            const float4 u2 = __ldg(u2row + i);
            if (c != 0u) {
                // c==1: exp(leaky(s+d+p_i-p_j)) via same fmax product form
                e.x = fmaxf(u.x * w.x, u2.x * w2.x);
                e.y = fmaxf(u.y * w.y, u2.y * w2.y);
                e.z = fmaxf(u.z * w.z, u2.z * w2.z);
                e.w = fmaxf(u.w * w.w, u2.w * w2.w);
                if (c > 1u) {   // duplicate edges: rare exact path
                    const int ri = b * Nn + i0 + i;
                    const float4 s  = __ldg(&g_S[ri]);
                    const float4 pi = __ldg(&g_P[ri]);
                    const float4 dj = __ldg(&g_D[rj]);
                    const float4 pj = __ldg(&g_P[rj]);
                    const float fc = (float)c;
                    float vx = s.x + dj.x + fc * (pi.x - pj.x);
                    float vy = s.y + dj.y + fc * (pi.y - pj.y);
                    float vz = s.z + dj.z + fc * (pi.z - pj.z);
                    float vw = s.w + dj.w + fc * (pi.w - pj.w);
                    vx = (vx > 0.0f) ? vx : NEG * vx;
                    vy = (vy > 0.0f) ? vy : NEG * vy;
                    vz = (vz > 0.0f) ? vz : NEG * vz;
                    vw = (vw > 0.0f) ? vw : NEG * vw;
                    e.x = __expf(vx); e.y = __expf(vy);
                    e.z = __expf(vz); e.w = __expf(vw);
                }
            }
        }

        const float inv = __fdividef(1.0f, (e.x + e.y) + (e.z + e.w));
        __stcs(optr + (size_t)i * Nn,
               make_float4(e.x * inv, e.y * inv, e.z * inv, e.w * inv));
    }
}

// ---------------------------------------------------------------------------
// Launch
// Inputs (metadata order): src, edge_index, W_lin, a_src, a_dst, W_edge, a_edge
// ---------------------------------------------------------------------------
extern "C" void kernel_launch(void* const* d_in, const int* in_sizes, int n_in,
                              void* d_out, int out_size) {
    const float* src        = (const float*)d_in[0];
    const int*   edge_index = (const int*)  d_in[1];
    const float* W_lin      = (const float*)d_in[2];
    const float* a_src      = (const float*)d_in[3];
    const float* a_dst      = (const float*)d_in[4];
    const float* W_edge     = (const float*)d_in[5];
    const float* a_edge     = (const float*)d_in[6];
    const int E = in_sizes[1] / 2;

    prep_kernel<<<256, 256>>>(src, edge_index, E,
                              W_lin, a_src, a_dst, W_edge, a_edge);
    attn_main_kernel<<<dim3(Nn / 256, Nn / ICHUNK, Bn), 256>>>((float4*)d_out);
}

// round 14
// speedup vs baseline: 1.5481x; 1.5481x over previous
#include <cuda_runtime.h>
#include <cuda_bf16.h>
#include <cstdint>

// Problem constants (fixed shapes per reference)
#define Bn   8
#define Nn   1024
#define Fin  128
#define Cc   128
#define Ef   64
#define Hh   4
#define NEG  0.2f
#define ROWS (Bn * 1024)        // 8192
#define ICHUNK 16               // i-rows per block in main kernel
#define NBKT   256              // (64 i-chunks) x (4 j-tiles)
#define BCAP   1024             // bucket capacity (mean occupancy ~128)

// Scratch (device globals — no allocation allowed)
__device__ float          g_M[Fin * 12];    // cols 0-3: As, 4-7: Ad, 8-11: Ae
__device__ float4         g_S  [ROWS];      // s = src @ (W_lin@a_src)
__device__ float4         g_D  [ROWS];      // d = src @ (W_lin@a_dst)
__device__ float4         g_P  [ROWS];      // p = src @ (W_edge@a_edge)
__device__ float4         g_ES [ROWS];      // exp(s)
__device__ float4         g_ES2[ROWS];      // exp(0.2 s)
__device__ float4         g_ED [ROWS];      // exp(d)
__device__ float4         g_ED2[ROWS];      // exp(0.2 d)
__device__ float4         g_U  [ROWS];      // exp(s + p)
__device__ float4         g_U2 [ROWS];      // exp(0.2(s + p))
__device__ float4         g_W  [ROWS];      // exp(d - p)
__device__ float4         g_W2 [ROWS];      // exp(0.2(d - p))
__device__ int            g_bcnt[NBKT];     // per-tile edge counts
__device__ unsigned short g_bdata[NBKT * BCAP];  // packed cells: i_loc<<8 | j_loc

// ---------------------------------------------------------------------------
// Kernel 1: fold weights — warp-per-entry. 1536 entries = 1536 warps =
// 192 blocks x 8 warps (validated R12: 4.48us, correct). Block 0 zeroes
// the 256 bucket counters.
// ---------------------------------------------------------------------------
__global__ __launch_bounds__(256) void m_zero_kernel(
        const float* __restrict__ W_lin,
        const float* __restrict__ a_src,
        const float* __restrict__ a_dst,
        const float* __restrict__ W_edge,
        const float* __restrict__ a_edge) {
    const int t = blockIdx.x * blockDim.x + threadIdx.x;

    if (blockIdx.x == 0) g_bcnt[threadIdx.x] = 0;

    const int gw   = t >> 5;      // 0..1535
    const int lane = t & 31;
    const int f   = gw / 12;      // 0..127
    const int col = gw % 12;
    float acc = 0.0f;
    if (col < 8) {
        const float* __restrict__ av = (col < 4) ? a_src : a_dst;
        const int h = col & 3;
        #pragma unroll
        for (int k = 0; k < 4; k++) {
            const int c = lane + k * 32;
            acc += W_lin[f * Cc + c] * av[c * Hh + h];
        }
    } else {
        const int h = col - 8;
        #pragma unroll
        for (int k = 0; k < 2; k++) {
            const int d = lane + k * 32;
            acc += W_edge[f * Ef + d] * a_edge[d * Hh + h];
        }
    }
    #pragma unroll
    for (int o = 16; o > 0; o >>= 1) acc += __shfl_xor_sync(0xffffffffu, acc, o);
    if (lane == 0) g_M[f * 12 + col] = acc;
}

// ---------------------------------------------------------------------------
// Kernel 2: bucket edges by output tile + warp-per-row projections & exps.
// (validated R12)
// ---------------------------------------------------------------------------
__global__ __launch_bounds__(256) void rows_bucket_kernel(
        const float* __restrict__ src,
        const int*   __restrict__ edge_index, int E) {
    // ---- bucketing: tile = (i>>4, j>>8) -> bucket, store packed local cell
    {
        const int t  = blockIdx.x * blockDim.x + threadIdx.x;
        const int nt = gridDim.x * blockDim.x;
        for (int e = t; e < E; e += nt) {
            const int i = edge_index[e];
            const int j = edge_index[E + e];
            const int bkt = (i >> 4) * 4 + (j >> 8);
            const int pos = atomicAdd(&g_bcnt[bkt], 1);
            if (pos < BCAP)
                g_bdata[bkt * BCAP + pos] =
                    (unsigned short)(((i & 15) << 8) | (j & 255));
        }
    }

    // ---- rows
    __shared__ float sM[Fin * 12];
    for (int idx = threadIdx.x; idx < Fin * 12; idx += 256) sM[idx] = g_M[idx];
    __syncthreads();

    const int gwarp  = (blockIdx.x * blockDim.x + threadIdx.x) >> 5;
    const int lane   = threadIdx.x & 31;
    const int nwarps = (gridDim.x * blockDim.x) >> 5;

    for (int r = gwarp; r < ROWS; r += nwarps) {
        const float4 sv = reinterpret_cast<const float4*>(src + (size_t)r * Fin)[lane];
        float acc[12];
        #pragma unroll
        for (int h = 0; h < 12; h++) acc[h] = 0.0f;

        const float vals[4] = {sv.x, sv.y, sv.z, sv.w};
        #pragma unroll
        for (int k = 0; k < 4; k++) {
            const int f = lane * 4 + k;
            const float x = vals[k];
            #pragma unroll
            for (int h = 0; h < 12; h++) acc[h] += x * sM[f * 12 + h];
        }
        #pragma unroll
        for (int o = 16; o > 0; o >>= 1) {
            #pragma unroll
            for (int h = 0; h < 12; h++)
                acc[h] += __shfl_xor_sync(0xffffffffu, acc[h], o);
        }
        if (lane == 0) {
            float4 s = make_float4(acc[0], acc[1], acc[2],  acc[3]);
            float4 d = make_float4(acc[4], acc[5], acc[6],  acc[7]);
            float4 p = make_float4(acc[8], acc[9], acc[10], acc[11]);
            g_S[r] = s;  g_D[r] = d;  g_P[r] = p;
            g_ES [r] = make_float4(__expf(s.x), __expf(s.y), __expf(s.z), __expf(s.w));
            g_ES2[r] = make_float4(__expf(NEG*s.x), __expf(NEG*s.y), __expf(NEG*s.z), __expf(NEG*s.w));
            g_ED [r] = make_float4(__expf(d.x), __expf(d.y), __expf(d.z), __expf(d.w));
            g_ED2[r] = make_float4(__expf(NEG*d.x), __expf(NEG*d.y), __expf(NEG*d.z), __expf(NEG*d.w));
            float4 sp = make_float4(s.x + p.x, s.y + p.y, s.z + p.z, s.w + p.w);
            float4 dp = make_float4(d.x - p.x, d.y - p.y, d.z - p.z, d.w - p.w);
            g_U [r] = make_float4(__expf(sp.x), __expf(sp.y), __expf(sp.z), __expf(sp.w));
            g_U2[r] = make_float4(__expf(NEG*sp.x), __expf(NEG*sp.y), __expf(NEG*sp.z), __expf(NEG*sp.w));
            g_W [r] = make_float4(__expf(dp.x), __expf(dp.y), __expf(dp.z), __expf(dp.w));
            g_W2[r] = make_float4(__expf(NEG*dp.x), __expf(NEG*dp.y), __expf(NEG*dp.z), __expf(NEG*dp.w));
        }
    }
}

// ---------------------------------------------------------------------------
// Kernel 3: fused MAIN with once-per-warp edge mask.
// Block = (j-tile, i-chunk, b). Builds the 4 KB smem multiplicity tile,
// then each warp computes a 16-bit mask of which i-iters contain any edge
// in its 32-j window (ONE ballot). ~78% of warp-iters run the pure
// 2-stream fmax body; edge iters select the (u,w) table pair; c>=2 takes
// the exact __expf path. Output written once, fully coalesced.
// ---------------------------------------------------------------------------
__global__ __launch_bounds__(256) void attn_main_kernel(float4* __restrict__ out) {
    __shared__ unsigned scnt[1024];            // uint8[16][256] packed

    const int jt = blockIdx.x;                 // 0..3
    const int ic = blockIdx.y;                 // 0..63
    const int b  = blockIdx.z;
    const int j  = jt * 256 + threadIdx.x;
    const int i0 = ic * ICHUNK;
    const int rj = b * Nn + j;

    // build smem cnt from this tile's bucket
    #pragma unroll
    for (int k = 0; k < 4; k++) scnt[threadIdx.x + k * 256] = 0u;
    __syncthreads();
    {
        const int bkt = ic * 4 + jt;
        const int n = g_bcnt[bkt] < BCAP ? g_bcnt[bkt] : BCAP;
        for (int k = threadIdx.x; k < n; k += 256) {
            const unsigned cell = g_bdata[bkt * BCAP + k];   // i_loc<<8 | j_loc
            atomicAdd(&scnt[cell >> 2], 1u << ((cell & 3) * 8));
        }
    }
    __syncthreads();
    const unsigned char* sc8 = reinterpret_cast<const unsigned char*>(scnt);

    // once-per-warp: 16-bit mask of i-iters with any edge in this warp's
    // 32-j window. Lane l (l<16) ORs row l's 8 words; single ballot.
    const int wid  = threadIdx.x >> 5;
    const int lane = threadIdx.x & 31;
    unsigned pred = 0u;
    if (lane < ICHUNK) {
        const unsigned* wptr = &scnt[(lane << 6) + (wid << 3)];  // row*64 + wid*8
        unsigned acc = 0u;
        #pragma unroll
        for (int k = 0; k < 8; k++) acc |= wptr[k];
        pred = acc;
    }
    const unsigned imask = __ballot_sync(0xffffffffu, pred != 0u);

    // j-side tables in registers
    const float4 ed  = __ldg(&g_ED [rj]);
    const float4 ed2 = __ldg(&g_ED2[rj]);
    const float4 w   = __ldg(&g_W  [rj]);
    const float4 w2  = __ldg(&g_W2 [rj]);

    const float4* __restrict__ esrow  = g_ES  + b * Nn + i0;
    const float4* __restrict__ es2row = g_ES2 + b * Nn + i0;
    const float4* __restrict__ urow   = g_U   + b * Nn + i0;
    const float4* __restrict__ u2row  = g_U2  + b * Nn + i0;
    float4* __restrict__ optr = out + ((size_t)(b * Nn + i0)) * Nn + j;

    #pragma unroll 4
    for (int i = 0; i < ICHUNK; i++) {
        const float4 es  = __ldg(esrow  + i);   // broadcast across warp
        const float4 es2 = __ldg(es2row + i);

        float4 e;
        e.x = fmaxf(es.x * ed.x, es2.x * ed2.x);
        e.y = fmaxf(es.y * ed.y, es2.y * ed2.y);
        e.z = fmaxf(es.z * ed.z, es2.z * ed2.z);
        e.w = fmaxf(es.w * ed.w, es2.w * ed2.w);

        if (imask & (1u << i)) {   // warp-uniform; ~22% of iters
            const unsigned c = sc8[i * 256 + threadIdx.x];
            const float4 u  = __ldg(urow  + i);
            const float4 u2 = __ldg(u2row + i);
            if (c != 0u) {
                // c==1: exp(leaky(s+d+p_i-p_j)) via same fmax product form
                e.x = fmaxf(u.x * w.x, u2.x * w2.x);
                e.y = fmaxf(u.y * w.y, u2.y * w2.y);
                e.z = fmaxf(u.z * w.z, u2.z * w2.z);
                e.w = fmaxf(u.w * w.w, u2.w * w2.w);
                if (c > 1u) {   // duplicate edges: rare exact path
                    const int ri = b * Nn + i0 + i;
                    const float4 s  = __ldg(&g_S[ri]);
                    const float4 pi = __ldg(&g_P[ri]);
                    const float4 dj = __ldg(&g_D[rj]);
                    const float4 pj = __ldg(&g_P[rj]);
                    const float fc = (float)c;
                    float vx = s.x + dj.x + fc * (pi.x - pj.x);
                    float vy = s.y + dj.y + fc * (pi.y - pj.y);
                    float vz = s.z + dj.z + fc * (pi.z - pj.z);
                    float vw = s.w + dj.w + fc * (pi.w - pj.w);
                    vx = (vx > 0.0f) ? vx : NEG * vx;
                    vy = (vy > 0.0f) ? vy : NEG * vy;
                    vz = (vz > 0.0f) ? vz : NEG * vz;
                    vw = (vw > 0.0f) ? vw : NEG * vw;
                    e.x = __expf(vx); e.y = __expf(vy);
                    e.z = __expf(vz); e.w = __expf(vw);
                }
            }
        }

        const float inv = __fdividef(1.0f, (e.x + e.y) + (e.z + e.w));
        __stcs(optr + (size_t)i * Nn,
               make_float4(e.x * inv, e.y * inv, e.z * inv, e.w * inv));
    }
}

// ---------------------------------------------------------------------------
// Launch
// Inputs (metadata order): src, edge_index, W_lin, a_src, a_dst, W_edge, a_edge
// ---------------------------------------------------------------------------
extern "C" void kernel_launch(void* const* d_in, const int* in_sizes, int n_in,
                              void* d_out, int out_size) {
    const float* src        = (const float*)d_in[0];
    const int*   edge_index = (const int*)  d_in[1];
    const float* W_lin      = (const float*)d_in[2];
    const float* a_src      = (const float*)d_in[3];
    const float* a_dst      = (const float*)d_in[4];
    const float* W_edge     = (const float*)d_in[5];
    const float* a_edge     = (const float*)d_in[6];
    const int E = in_sizes[1] / 2;

    m_zero_kernel<<<192, 256>>>(W_lin, a_src, a_dst, W_edge, a_edge);
    rows_bucket_kernel<<<256, 256>>>(src, edge_index, E);
    attn_main_kernel<<<dim3(Nn / 256, Nn / ICHUNK, Bn), 256>>>((float4*)d_out);
}